// round 8
// baseline (speedup 1.0000x reference)
#include <cuda_runtime.h>

// DisentanglementModule contrastive loss, reduced analytically:
//   loss_x = S_pos/c_pos - S_neg/c_neg  (tau terms cancel; torch.max on 0-dim is identity -> no hinge)
//   S_pos  = (sum_k n_k*s_k - sum_k ||m_k||^2) / d
//   S_all  = (B*sum_k s_k - ||sum_k m_k||^2) / d ;  S_neg = S_all - S_pos
// m_k = per-class column sums, s_k = per-class sum of squares, n_k = class counts.
// O(B*d) streaming (~23 MB), fused into ONE launch: 192 blocks accumulate
// per-block partials (no global atomics, no zero pass), last-arriving block
// reduces partials and writes the scalar. Counter self-resets -> graph-safe.

#define BATCH    4096
#define NCLS     4
#define D_REP    1024
#define D_A0     64
#define D_A1     128
#define D_A2     256
#define NCOLS    (D_REP + D_A0 + D_A1 + D_A2)   // 1472
#define ROWCHUNK 128
#define NTHREADS 256
#define NBX      6                               // ceil(1536/256) col tiles
#define NBY      (BATCH / ROWCHUNK)              // 32 row chunks
#define NBLK     (NBX * NBY)                     // 192

// Scratch (device globals: allocations are forbidden).
// g_pm fully overwritten every launch -> no zeroing required.
__device__ float4   g_pm[NBLK * NTHREADS];  // [block][tid] -> {m0,m1,m2,m3} partial col sums
__device__ double   g_ps[NBLK][16];         // [block][fs*4+cls] partial sq sums
__device__ unsigned g_count = 0;            // arrival counter; last block resets to 0

__device__ __forceinline__ int class_of(const void* nl, int i, int is32) {
    return is32 ? ((const int*)nl)[i] : (int)((const long long*)nl)[i];
}

__global__ void __launch_bounds__(NTHREADS)
fused_kernel(const float* __restrict__ rep,
             const float* __restrict__ a0,
             const float* __restrict__ a1,
             const float* __restrict__ a2,
             const void*  __restrict__ nl,
             float*       __restrict__ out)
{
    __shared__ int    cls[ROWCHUNK];
    __shared__ double sh16[16];     // per-block [fs][cls] sq-sum reduce
    __shared__ int    sh_last;

    const int tid = threadIdx.x;
    const int bx  = blockIdx.x;
    const int by  = blockIdx.y;
    const int blk = bx * NBY + by;
    const int col = bx * NTHREADS + tid;
    const int r0  = by * ROWCHUNK;

    // ---- dtype probe: first 2048 odd int32 words (16 KB total span; in-bounds
    // for either dtype). int64 values 0..3 => all odd words zero.
    int odd = 0;
    for (int i = tid; i < 2048; i += NTHREADS)
        odd |= (((const int*)nl)[2 * i + 1] != 0);
    const int is32 = __syncthreads_or(odd);

    for (int i = tid; i < ROWCHUNK; i += NTHREADS) cls[i] = class_of(nl, r0 + i, is32);
    if (tid < 16) sh16[tid] = 0.0;
    __syncthreads();

    // Concatenated column index -> (feature set, source, leading dim, local col)
    const float* src; int ld, c, fs;
    if (col < D_REP)                    { fs = 0; src = rep; ld = 1024; c = col; }
    else if (col < D_REP + D_A0)        { fs = 1; src = a0;  ld = 512;  c = col - D_REP; }
    else if (col < D_REP + D_A0 + D_A1) { fs = 2; src = a1;  ld = 512;  c = col - (D_REP + D_A0); }
    else                                { fs = 3; src = a2;  ld = 512;  c = col - (D_REP + D_A0 + D_A1); }
    const bool valid = (col < NCOLS);

    float m0 = 0.f, m1 = 0.f, m2 = 0.f, m3 = 0.f;
    float s0 = 0.f, s1 = 0.f, s2 = 0.f, s3 = 0.f;

    if (valid) {
        const float* p = src + (long)r0 * ld + c;
        #pragma unroll 8
        for (int i = 0; i < ROWCHUNK; i++) {
            float x  = p[(long)i * ld];   // coalesced: lanes = consecutive columns
            int   cc = cls[i];            // warp-uniform (class is per-row)
            float x2 = x * x;
            if      (cc == 0) { m0 += x; s0 += x2; }
            else if (cc == 1) { m1 += x; s1 += x2; }
            else if (cc == 2) { m2 += x; s2 += x2; }
            else              { m3 += x; s3 += x2; }
        }
    }
    // Per-block column partials (tail cols write zeros). One STG.128, no atomics.
    g_pm[blk * NTHREADS + tid] = make_float4(m0, m1, m2, m3);

    // Warp-reduce sq sums. fs is warp-uniform: boundaries 1024/1088/1216 are
    // multiples of 32; the invalid tail (cols 1472..1535) has fs==3 and zeros.
    #pragma unroll
    for (int off = 16; off > 0; off >>= 1) {
        s0 += __shfl_down_sync(0xffffffffu, s0, off);
        s1 += __shfl_down_sync(0xffffffffu, s1, off);
        s2 += __shfl_down_sync(0xffffffffu, s2, off);
        s3 += __shfl_down_sync(0xffffffffu, s3, off);
    }
    if ((tid & 31) == 0) {
        atomicAdd(&sh16[fs * 4 + 0], (double)s0);
        atomicAdd(&sh16[fs * 4 + 1], (double)s1);
        atomicAdd(&sh16[fs * 4 + 2], (double)s2);
        atomicAdd(&sh16[fs * 4 + 3], (double)s3);
    }
    __syncthreads();
    if (tid < 16) g_ps[blk][tid] = sh16[tid];

    // ---- arrive; last block finalizes ----
    __threadfence();
    if (tid == 0) {
        unsigned v = atomicAdd(&g_count, 1u);
        sh_last = (v == NBLK - 1);
    }
    __syncthreads();
    if (!sh_last) return;

    // ======================= FINALIZE (one block) =======================
    __shared__ double fa[4][NCLS];  // per-fs ||m_k||^2 per class
    __shared__ double fb[4];        // per-fs ||sum_k m_k||^2
    __shared__ double fsq[16];      // total sq sums [fs][cls]
    __shared__ int    fn[NCLS];

    if (tid < 16) { ((double*)fa)[tid] = 0.0; fsq[tid] = 0.0; }
    if (tid < 4)  fb[tid] = 0.0;
    if (tid < NCLS) fn[tid] = 0;
    __syncthreads();

    // class counts
    {
        int c0 = 0, c1 = 0, c2 = 0, c3 = 0;
        for (int i = tid; i < BATCH; i += NTHREADS) {
            int cc = class_of(nl, i, is32);
            c0 += (cc == 0); c1 += (cc == 1); c2 += (cc == 2); c3 += (cc == 3);
        }
        #pragma unroll
        for (int off = 16; off > 0; off >>= 1) {
            c0 += __shfl_down_sync(0xffffffffu, c0, off);
            c1 += __shfl_down_sync(0xffffffffu, c1, off);
            c2 += __shfl_down_sync(0xffffffffu, c2, off);
            c3 += __shfl_down_sync(0xffffffffu, c3, off);
        }
        if ((tid & 31) == 0) {
            atomicAdd(&fn[0], c0); atomicAdd(&fn[1], c1);
            atomicAdd(&fn[2], c2); atomicAdd(&fn[3], c3);
        }
    }

    // total sq sums: 16 entries x 192 blocks (L2-resident)
    if (tid < 16) {
        double t = 0.0;
        for (int b = 0; b < NBLK; b++) t += g_ps[b][tid];
        fsq[tid] = t;
    }

    // ||m_k||^2 and ||M||^2 per feature set; m_k from 32 by-partials (fp64 acc)
    const int base[5] = {0, D_REP, D_REP + D_A0, D_REP + D_A0 + D_A1, NCOLS};
    for (int f = 0; f < 4; f++) {
        double a0_ = 0, a1_ = 0, a2_ = 0, a3_ = 0, b_ = 0;
        for (int cc = base[f] + tid; cc < base[f + 1]; cc += NTHREADS) {
            const int cbx = cc >> 8, cti = cc & 255;
            double v0 = 0, v1 = 0, v2 = 0, v3 = 0;
            #pragma unroll 4
            for (int y = 0; y < NBY; y++) {
                float4 p = g_pm[(cbx * NBY + y) * NTHREADS + cti];  // LDG.128, L2-hit
                v0 += (double)p.x; v1 += (double)p.y;
                v2 += (double)p.z; v3 += (double)p.w;
            }
            a0_ += v0 * v0; a1_ += v1 * v1; a2_ += v2 * v2; a3_ += v3 * v3;
            double M = v0 + v1 + v2 + v3;
            b_ += M * M;
        }
        #pragma unroll
        for (int off = 16; off > 0; off >>= 1) {
            a0_ += __shfl_down_sync(0xffffffffu, a0_, off);
            a1_ += __shfl_down_sync(0xffffffffu, a1_, off);
            a2_ += __shfl_down_sync(0xffffffffu, a2_, off);
            a3_ += __shfl_down_sync(0xffffffffu, a3_, off);
            b_  += __shfl_down_sync(0xffffffffu, b_,  off);
        }
        if ((tid & 31) == 0) {
            atomicAdd(&fa[f][0], a0_); atomicAdd(&fa[f][1], a1_);
            atomicAdd(&fa[f][2], a2_); atomicAdd(&fa[f][3], a3_);
            atomicAdd(&fb[f], b_);
        }
    }
    __syncthreads();

    if (tid == 0) {
        double n[NCLS];
        for (int k = 0; k < NCLS; k++) n[k] = (double)fn[k];
        double cpos = 0.0;
        for (int k = 0; k < NCLS; k++) cpos += 0.5 * n[k] * (n[k] - 1.0);
        double cneg = 0.5 * (double)BATCH * (double)(BATCH - 1) - cpos;

        const int dims[4] = {D_REP, D_A0, D_A1, D_A2};
        double losses[4];
        for (int f = 0; f < 4; f++) {
            double nss = 0.0, mm = 0.0, stot = 0.0;
            for (int k = 0; k < NCLS; k++) {
                nss  += n[k] * fsq[f * 4 + k];
                mm   += fa[f][k];
                stot += fsq[f * 4 + k];
            }
            double Spos = (nss - mm) / (double)dims[f];
            double Sall = ((double)BATCH * stot - fb[f]) / (double)dims[f];
            double Sneg = Sall - Spos;
            losses[f] = Spos / cpos - Sneg / cneg;   // tau_pos == tau_neg cancels
        }
        double latent = (losses[1] + losses[2] + losses[3]) / 3.0;
        out[0] = (float)(0.5 * latent + 0.5 * losses[0]);
        g_count = 0;   // reset for next launch / graph replay (deterministic)
    }
}

extern "C" void kernel_launch(void* const* d_in, const int* in_sizes, int n_in,
                              void* d_out, int out_size)
{
    (void)in_sizes; (void)n_in; (void)out_size;
    const float* rep = (const float*)d_in[0];
    const float* a0  = (const float*)d_in[1];
    const float* a1  = (const float*)d_in[2];
    const float* a2  = (const float*)d_in[3];
    const void*  nl  = d_in[4];

    dim3 grid(NBX, NBY);   // 6 x 32 = 192 blocks
    fused_kernel<<<grid, NTHREADS>>>(rep, a0, a1, a2, nl, (float*)d_out);
}

// round 13
// speedup vs baseline: 3.1866x; 3.1866x over previous
#include <cuda_runtime.h>

// DisentanglementModule contrastive loss, reduced analytically:
//   loss_x = S_pos/c_pos - S_neg/c_neg  (tau terms cancel; no hinge in reference)
//   S_pos  = (sum_k n_k*s_k - sum_k ||m_k||^2) / d
//   S_all  = (B*sum_k s_k - ||sum_k m_k||^2) / d ;  S_neg = S_all - S_pos
// Single launch. R8 ncu showed MLP_eff<1 (DRAM 1.5%, 172us): loads were
// serialized behind per-row branches. v2: float4 loads, explicit 8-deep load
// batches (branch-free), 384 CTAs, RED.ADD column sums straight into g_m.
// Finalize block zeroes scratch after use -> launch invariant, graph-safe.

#define BATCH    4096
#define NCLS     4
#define D_REP    1024
#define D_A0     64
#define D_A1     128
#define D_A2     256
#define NCOLS    (D_REP + D_A0 + D_A1 + D_A2)   // 1472
#define ROWCHUNK 32
#define NTHREADS 128
#define NBX      3
#define NBY      (BATCH / ROWCHUNK)              // 128
#define NBLK     (NBX * NBY)                     // 384

// Scratch (device globals; zero-initialized at load, re-zeroed by finalize).
__device__ float    g_m[NCLS][NCOLS];   // per-class column sums
__device__ double   g_s[16];            // [fs*4+cls] sum of squares
__device__ unsigned g_count;            // arrival counter; finalize resets

__device__ __forceinline__ int class_of(const void* nl, int i, int is32) {
    return is32 ? ((const int*)nl)[i] : (int)((const long long*)nl)[i];
}

__global__ void __launch_bounds__(NTHREADS)
fused_kernel(const float* __restrict__ rep,
             const float* __restrict__ a0,
             const float* __restrict__ a1,
             const float* __restrict__ a2,
             const void*  __restrict__ nl,
             float*       __restrict__ out)
{
    __shared__ int   cls[ROWCHUNK];
    __shared__ float sh_s[16];
    __shared__ int   sh_last;

    const int tid = threadIdx.x;
    const int bx  = blockIdx.x;
    const int by  = blockIdx.y;
    const int r0  = by * ROWCHUNK;

    // dtype probe: odd int32 words of first 128 entries (1 KB; in-bounds for
    // int32 or int64 buffer). int64 values 0..3 => odd words all zero.
    int odd = (((const int*)nl)[2 * tid + 1] != 0);
    const int is32 = __syncthreads_or(odd);

    if (tid < ROWCHUNK) cls[tid] = class_of(nl, r0 + tid, is32);
    if (tid < 16) sh_s[tid] = 0.0f;
    __syncthreads();

    // Column-tile mapping (float4 granularity).
    //  bx=0: rep cols [0,512)    bx=1: rep cols [512,1024)
    //  bx=2: a0|a1|a2 (448 cols => 112 groups; threads 112..127 idle)
    const float4* src4; int ld4, g4, fs, gcol; bool valid = true;
    if (bx == 0)      { fs = 0; src4 = (const float4*)rep; ld4 = 256; g4 = tid;        gcol = 4 * tid; }
    else if (bx == 1) { fs = 0; src4 = (const float4*)rep; ld4 = 256; g4 = 128 + tid;  gcol = 512 + 4 * tid; }
    else {
        ld4 = 128;
        if (tid < 16)       { fs = 1; src4 = (const float4*)a0; g4 = tid;       gcol = 1024 + 4 * tid; }
        else if (tid < 48)  { fs = 2; src4 = (const float4*)a1; g4 = tid - 16;  gcol = 1088 + 4 * (tid - 16); }
        else if (tid < 112) { fs = 3; src4 = (const float4*)a2; g4 = tid - 48;  gcol = 1216 + 4 * (tid - 48); }
        else                { fs = 3; src4 = (const float4*)a2; g4 = 0; gcol = 0; valid = false; }
    }

    float4 m0 = {0,0,0,0}, m1 = {0,0,0,0}, m2 = {0,0,0,0}, m3 = {0,0,0,0};
    float  s0 = 0.f, s1 = 0.f, s2 = 0.f, s3 = 0.f;

    if (valid) {
        const float4* p = src4 + (size_t)r0 * ld4 + g4;
        #pragma unroll
        for (int batch = 0; batch < ROWCHUNK; batch += 8) {
            // Branch-free load block: 8 independent LDG.128 in flight.
            float4 xs[8];
            #pragma unroll
            for (int j = 0; j < 8; j++)
                xs[j] = p[(size_t)(batch + j) * ld4];
            // Accumulate (class branch is block-uniform: per-row).
            #pragma unroll
            for (int j = 0; j < 8; j++) {
                const float4 x = xs[j];
                const int    cc = cls[batch + j];
                const float  q = x.x*x.x + x.y*x.y + x.z*x.z + x.w*x.w;
                if      (cc == 0) { m0.x+=x.x; m0.y+=x.y; m0.z+=x.z; m0.w+=x.w; s0+=q; }
                else if (cc == 1) { m1.x+=x.x; m1.y+=x.y; m1.z+=x.z; m1.w+=x.w; s1+=q; }
                else if (cc == 2) { m2.x+=x.x; m2.y+=x.y; m2.z+=x.z; m2.w+=x.w; s2+=q; }
                else              { m3.x+=x.x; m3.y+=x.y; m3.z+=x.z; m3.w+=x.w; s3+=q; }
            }
        }
        // RED.ADD column sums (no return; spread addresses).
        atomicAdd(&g_m[0][gcol+0], m0.x); atomicAdd(&g_m[0][gcol+1], m0.y);
        atomicAdd(&g_m[0][gcol+2], m0.z); atomicAdd(&g_m[0][gcol+3], m0.w);
        atomicAdd(&g_m[1][gcol+0], m1.x); atomicAdd(&g_m[1][gcol+1], m1.y);
        atomicAdd(&g_m[1][gcol+2], m1.z); atomicAdd(&g_m[1][gcol+3], m1.w);
        atomicAdd(&g_m[2][gcol+0], m2.x); atomicAdd(&g_m[2][gcol+1], m2.y);
        atomicAdd(&g_m[2][gcol+2], m2.z); atomicAdd(&g_m[2][gcol+3], m2.w);
        atomicAdd(&g_m[3][gcol+0], m3.x); atomicAdd(&g_m[3][gcol+1], m3.y);
        atomicAdd(&g_m[3][gcol+2], m3.z); atomicAdd(&g_m[3][gcol+3], m3.w);
        // Sq-sum partials into shared (fs not warp-uniform in bx=2).
        atomicAdd(&sh_s[fs * 4 + 0], s0);
        atomicAdd(&sh_s[fs * 4 + 1], s1);
        atomicAdd(&sh_s[fs * 4 + 2], s2);
        atomicAdd(&sh_s[fs * 4 + 3], s3);
    }
    __syncthreads();
    if (tid < 16 && sh_s[tid] != 0.0f) atomicAdd(&g_s[tid], (double)sh_s[tid]);

    // ---- arrive; last block finalizes ----
    __threadfence();
    if (tid == 0) {
        unsigned v = atomicAdd(&g_count, 1u);
        sh_last = (v == NBLK - 1);
    }
    __syncthreads();
    if (!sh_last) return;

    // ======================= FINALIZE (one block) =======================
    __shared__ double fa[4][NCLS];  // per-fs ||m_k||^2 per class
    __shared__ double fb[4];        // per-fs ||sum_k m_k||^2
    __shared__ double fsq[16];
    __shared__ int    fn[NCLS];

    if (tid < 16) { ((double*)fa)[tid] = 0.0; fsq[tid] = g_s[tid]; }
    if (tid < 4)  fb[tid] = 0.0;
    if (tid < NCLS) fn[tid] = 0;
    __syncthreads();

    // class counts
    {
        int c0 = 0, c1 = 0, c2 = 0, c3 = 0;
        for (int i = tid; i < BATCH; i += NTHREADS) {
            int cc = class_of(nl, i, is32);
            c0 += (cc == 0); c1 += (cc == 1); c2 += (cc == 2); c3 += (cc == 3);
        }
        #pragma unroll
        for (int off = 16; off > 0; off >>= 1) {
            c0 += __shfl_down_sync(0xffffffffu, c0, off);
            c1 += __shfl_down_sync(0xffffffffu, c1, off);
            c2 += __shfl_down_sync(0xffffffffu, c2, off);
            c3 += __shfl_down_sync(0xffffffffu, c3, off);
        }
        if ((tid & 31) == 0) {
            atomicAdd(&fn[0], c0); atomicAdd(&fn[1], c1);
            atomicAdd(&fn[2], c2); atomicAdd(&fn[3], c3);
        }
    }

    // ||m_k||^2 and ||M||^2 per feature set (g_m is 23 KB, L2-resident)
    const int base[5] = {0, D_REP, D_REP + D_A0, D_REP + D_A0 + D_A1, NCOLS};
    for (int f = 0; f < 4; f++) {
        double a0_ = 0, a1_ = 0, a2_ = 0, a3_ = 0, b_ = 0;
        for (int cc = base[f] + tid; cc < base[f + 1]; cc += NTHREADS) {
            double v0 = (double)g_m[0][cc];
            double v1 = (double)g_m[1][cc];
            double v2 = (double)g_m[2][cc];
            double v3 = (double)g_m[3][cc];
            a0_ += v0 * v0; a1_ += v1 * v1; a2_ += v2 * v2; a3_ += v3 * v3;
            double M = v0 + v1 + v2 + v3;
            b_ += M * M;
        }
        #pragma unroll
        for (int off = 16; off > 0; off >>= 1) {
            a0_ += __shfl_down_sync(0xffffffffu, a0_, off);
            a1_ += __shfl_down_sync(0xffffffffu, a1_, off);
            a2_ += __shfl_down_sync(0xffffffffu, a2_, off);
            a3_ += __shfl_down_sync(0xffffffffu, a3_, off);
            b_  += __shfl_down_sync(0xffffffffu, b_,  off);
        }
        if ((tid & 31) == 0) {
            atomicAdd(&fa[f][0], a0_); atomicAdd(&fa[f][1], a1_);
            atomicAdd(&fa[f][2], a2_); atomicAdd(&fa[f][3], a3_);
            atomicAdd(&fb[f], b_);
        }
    }
    __syncthreads();

    if (tid == 0) {
        double n[NCLS];
        for (int k = 0; k < NCLS; k++) n[k] = (double)fn[k];
        double cpos = 0.0;
        for (int k = 0; k < NCLS; k++) cpos += 0.5 * n[k] * (n[k] - 1.0);
        double cneg = 0.5 * (double)BATCH * (double)(BATCH - 1) - cpos;

        const int dims[4] = {D_REP, D_A0, D_A1, D_A2};
        double losses[4];
        for (int f = 0; f < 4; f++) {
            double nss = 0.0, mm = 0.0, stot = 0.0;
            for (int k = 0; k < NCLS; k++) {
                nss  += n[k] * fsq[f * 4 + k];
                mm   += fa[f][k];
                stot += fsq[f * 4 + k];
            }
            double Spos = (nss - mm) / (double)dims[f];
            double Sall = ((double)BATCH * stot - fb[f]) / (double)dims[f];
            double Sneg = Sall - Spos;
            losses[f] = Spos / cpos - Sneg / cneg;   // tau_pos == tau_neg cancels
        }
        double latent = (losses[1] + losses[2] + losses[3]) / 3.0;
        out[0] = (float)(0.5 * latent + 0.5 * losses[0]);
    }
    __syncthreads();

    // Restore launch invariant for next graph replay (scratch back to zero).
    for (int i = tid; i < NCLS * NCOLS; i += NTHREADS) ((float*)g_m)[i] = 0.0f;
    if (tid < 16) g_s[tid] = 0.0;
    __threadfence();
    __syncthreads();
    if (tid == 0) g_count = 0;
}

extern "C" void kernel_launch(void* const* d_in, const int* in_sizes, int n_in,
                              void* d_out, int out_size)
{
    (void)in_sizes; (void)n_in; (void)out_size;
    const float* rep = (const float*)d_in[0];
    const float* a0  = (const float*)d_in[1];
    const float* a1  = (const float*)d_in[2];
    const float* a2  = (const float*)d_in[3];
    const void*  nl  = d_in[4];

    dim3 grid(NBX, NBY);   // 3 x 128 = 384 blocks
    fused_kernel<<<grid, NTHREADS>>>(rep, a0, a1, a2, nl, (float*)d_out);
}